// round 14
// baseline (speedup 1.0000x reference)
#include <cuda_runtime.h>
#include <cuda_bf16.h>
#include <math.h>

// Problem constants
#define NB     32      // batch
#define HQ     32
#define HKV    8
#define NREP   4
#define HD     128
#define DIM    4096    // HQ*HD
#define KVD    1024    // HKV*HD
#define MAXSEQ 4096
#define NEWPOS 4095

#define KSPLIT 32      // GEMM k-split
#define KB     128     // 4096 / KSPLIT
#define QKV_OUTS 6144  // 4096 + 1024 + 1024
#define NSPLIT 16      // attention seq splits
#define SCHUNK 256     // 4096 / 16

// ---------------- scratch (device globals; no allocations allowed) -------------
__device__ float g_qkv [NB * QKV_OUTS];             // qkv summed (atomic)
__device__ float g_q   [NB * DIM];                  // rope'd q
__device__ float g_kn  [NB * KVD];                  // rope'd new k
__device__ float g_vn  [NB * KVD];                  // new v
__device__ float g_pm  [NB * HKV * NSPLIT * NREP];  // partial max
__device__ float g_pl  [NB * HKV * NSPLIT * NREP];  // partial sum
__device__ float g_pacc[NB * HKV * NSPLIT * NREP * HD]; // partial acc
__device__ float g_attn[NB * DIM];                  // attention output

// ---------------- f32x2 helpers (attention only) ---------------------------------
__device__ __forceinline__ unsigned long long f2fma(unsigned long long a,
                                                    unsigned long long b,
                                                    unsigned long long c) {
    unsigned long long d;
    asm("fma.rn.f32x2 %0, %1, %2, %3;" : "=l"(d) : "l"(a), "l"(b), "l"(c));
    return d;
}
__device__ __forceinline__ float2 uf2(unsigned long long u) {
    float2 f;
    asm("mov.b64 {%0, %1}, %2;" : "=f"(f.x), "=f"(f.y) : "l"(u));
    return f;
}
__device__ __forceinline__ unsigned long long dupf(float p) {
    unsigned long long u;
    asm("mov.b64 %0, {%1, %1};" : "=l"(u) : "f"(p));
    return u;
}
__device__ __forceinline__ unsigned long long pack2(float a, float b) {
    unsigned long long u;
    asm("mov.b64 %0, {%1, %2};" : "=l"(u) : "f"(a), "f"(b));
    return u;
}

// ------------------------------------------------------------------------------
// Zero the atomic accumulation buffers: g_qkv (196608) + out (131072).
// grid 640 x 512 = 327680 threads.
// ------------------------------------------------------------------------------
__global__ void zero_bufs(float* __restrict__ qkv, float* __restrict__ out)
{
    const int i = blockIdx.x * 512 + threadIdx.x;
    if (i < NB * QKV_OUTS) qkv[i] = 0.f;
    else out[i - NB * QKV_OUTS] = 0.f;
}

// ------------------------------------------------------------------------------
// Scalar-FFMA GEMM with atomic k-split accumulation:
// yp[b][o] += sum_{k in split} x[b,k] * W[o,k].
// grid (OUTS/256, KSPLIT), 256 threads. Thread tile 4 o x 8 b.
// Double-buffered smem, one __syncthreads pair per k-tile, LDG prefetch.
// ------------------------------------------------------------------------------
__global__ __launch_bounds__(256)
void gemm_s(const float* __restrict__ x,
            const float* __restrict__ w0,
            const float* __restrict__ w1,
            const float* __restrict__ w2,
            int n0, int n1,
            float* __restrict__ yp, int OUTS)
{
    const int obase = blockIdx.x * 256;
    const float* wp;
    int orow;
    if (obase < n0)            { wp = w0; orow = obase; }
    else if (obase < n0 + n1)  { wp = w1; orow = obase - n0; }
    else                       { wp = w2; orow = obase - n0 - n1; }
    const int kb0 = blockIdx.y * KB;

    __shared__ __align__(16) float ws[2 * 16 * 264];  // [buf][k][o]
    __shared__ __align__(16) float xs[2 * 16 * 36];   // [buf][k][b]

    const int t    = threadIdx.x;
    const int lane = t & 31;
    const int w    = t >> 5;

    const int og = (w & 1) * 128 + lane * 4;   // 4 outs
    const int bq = (w >> 1) * 8;               // 8 batches

    const int lxb = t >> 2;          // x load: batch (t<128)
    const int lxk = (t & 3) * 4;     // x load: k offset

    float acc[4][8];
#pragma unroll
    for (int j = 0; j < 4; j++)
#pragma unroll
        for (int i = 0; i < 8; i++) acc[j][i] = 0.f;

    const int NT = KB / 16;

    float4 wv[4], xv;
#pragma unroll
    for (int q = 0; q < 4; q++)
        wv[q] = *(const float4*)&wp[(size_t)(orow + t) * 4096 + kb0 + q * 4];
    if (t < 128) xv = *(const float4*)&x[lxb * 4096 + kb0 + lxk];

    for (int kt = 0; kt < NT; kt++) {
        float* wsb = ws + (kt & 1) * (16 * 264);
        float* xsb = xs + (kt & 1) * (16 * 36);

#pragma unroll
        for (int q = 0; q < 4; q++) {
            wsb[(q * 4 + 0) * 264 + t] = wv[q].x;
            wsb[(q * 4 + 1) * 264 + t] = wv[q].y;
            wsb[(q * 4 + 2) * 264 + t] = wv[q].z;
            wsb[(q * 4 + 3) * 264 + t] = wv[q].w;
        }
        if (t < 128) {
            xsb[(lxk + 0) * 36 + lxb] = xv.x;
            xsb[(lxk + 1) * 36 + lxb] = xv.y;
            xsb[(lxk + 2) * 36 + lxb] = xv.z;
            xsb[(lxk + 3) * 36 + lxb] = xv.w;
        }
        __syncthreads();

        if (kt + 1 < NT) {
            const int kbase = kb0 + (kt + 1) * 16;
#pragma unroll
            for (int q = 0; q < 4; q++)
                wv[q] = *(const float4*)&wp[(size_t)(orow + t) * 4096 + kbase + q * 4];
            if (t < 128) xv = *(const float4*)&x[lxb * 4096 + kbase + lxk];
        }

#pragma unroll
        for (int kk = 0; kk < 16; kk++) {
            const float4 w4 = *(const float4*)&wsb[kk * 264 + og];
            const float4 xA = *(const float4*)&xsb[kk * 36 + bq];
            const float4 xB = *(const float4*)&xsb[kk * 36 + bq + 4];
            acc[0][0] += w4.x * xA.x; acc[0][1] += w4.x * xA.y;
            acc[0][2] += w4.x * xA.z; acc[0][3] += w4.x * xA.w;
            acc[0][4] += w4.x * xB.x; acc[0][5] += w4.x * xB.y;
            acc[0][6] += w4.x * xB.z; acc[0][7] += w4.x * xB.w;
            acc[1][0] += w4.y * xA.x; acc[1][1] += w4.y * xA.y;
            acc[1][2] += w4.y * xA.z; acc[1][3] += w4.y * xA.w;
            acc[1][4] += w4.y * xB.x; acc[1][5] += w4.y * xB.y;
            acc[1][6] += w4.y * xB.z; acc[1][7] += w4.y * xB.w;
            acc[2][0] += w4.z * xA.x; acc[2][1] += w4.z * xA.y;
            acc[2][2] += w4.z * xA.z; acc[2][3] += w4.z * xA.w;
            acc[2][4] += w4.z * xB.x; acc[2][5] += w4.z * xB.y;
            acc[2][6] += w4.z * xB.z; acc[2][7] += w4.z * xB.w;
            acc[3][0] += w4.w * xA.x; acc[3][1] += w4.w * xA.y;
            acc[3][2] += w4.w * xA.z; acc[3][3] += w4.w * xA.w;
            acc[3][4] += w4.w * xB.x; acc[3][5] += w4.w * xB.y;
            acc[3][6] += w4.w * xB.z; acc[3][7] += w4.w * xB.w;
        }
        __syncthreads();
    }

    // atomic accumulate into the summed output (k-split reduction in L2)
#pragma unroll
    for (int i = 0; i < 8; i++) {
        const int b = bq + i;
        float* dst = &yp[(size_t)b * OUTS + obase + og];
        atomicAdd(dst + 0, acc[0][i]);
        atomicAdd(dst + 1, acc[1][i]);
        atomicAdd(dst + 2, acc[2][i]);
        atomicAdd(dst + 3, acc[3][i]);
    }
}

// ------------------------------------------------------------------------------
// RoPE on the summed qkv. grid 384 x 256.
// ------------------------------------------------------------------------------
__global__ void rope_reduce(const float* __restrict__ qkv,
                            const float* __restrict__ fc,
                            const float* __restrict__ fs,
                            float* __restrict__ qout,
                            float* __restrict__ kout,
                            float* __restrict__ vout)
{
    const int idx = blockIdx.x * 256 + threadIdx.x;  // < 98304
    const int b  = idx / 3072;
    const int jp = idx % 3072;
    const int j0 = jp * 2;

    float v0 = qkv[(size_t)b * QKV_OUTS + j0];
    float v1 = qkv[(size_t)b * QKV_OUTS + j0 + 1];

    if (j0 < DIM + KVD) {
        const int i = jp & 63;
        const float c = fc[i], s_ = fs[i];
        const float re = v0 * c - v1 * s_;
        const float im = v0 * s_ + v1 * c;
        v0 = re; v1 = im;
    }
    if (j0 < DIM) {
        qout[b * DIM + j0] = v0;
        qout[b * DIM + j0 + 1] = v1;
    } else if (j0 < DIM + KVD) {
        kout[b * KVD + (j0 - DIM)] = v0;
        kout[b * KVD + (j0 - DIM) + 1] = v1;
    } else {
        vout[b * KVD + (j0 - DIM - KVD)] = v0;
        vout[b * KVD + (j0 - DIM - KVD) + 1] = v1;
    }
}

// ------------------------------------------------------------------------------
// Flash-decode split attention (one barrier per tile, double-buffered part).
// grid (256, 16), 256 threads, __ldcs streaming. smem ~48KB (4 CTA/SM).
// ------------------------------------------------------------------------------
__global__ __launch_bounds__(256, 4)
void attn_split(const float* __restrict__ q,
                const float* __restrict__ ck,
                const float* __restrict__ cv,
                float* __restrict__ pm,
                float* __restrict__ pl,
                float* __restrict__ pacc)
{
    const int bg = blockIdx.x;
    const int b = bg >> 3, g = bg & 7;
    const int split = blockIdx.y;
    const int t = threadIdx.x;
    const int lane = t & 31, w = t >> 5;
    const int sbase = split * SCHUNK;

    __shared__ __align__(16) float sm[12036];
    float* qs   = sm;              // [4][128]             512
    float* kbuf = sm + 512;        // 2 x [32][132]        8448  (aliased by pvp)
    float* sc   = sm + 8960;       // [4][256]             1024
    float* part = sm + 9984;       // 2 x [8][4][32]       2048
    float* mf   = sm + 12032;      // [4]
    float* pvp  = kbuf;            // alias, [8][4][128] = 4096

    const float scale = 0.08838834764831845f;  // 1/sqrt(128)

    for (int i = t; i < 512; i += 256) {
        const int r = i >> 7, d = i & 127;
        qs[r * 128 + d] = q[(b * HQ + g * NREP + r) * HD + d] * scale;
    }

    const int s_loc = t & 31;
    const int dg = t >> 5;
    const int base_d = dg * 16;
    const size_t ckb = (size_t)(b * MAXSEQ) * KVD + g * HD;

    float4 kreg[4];
#pragma unroll
    for (int i = 0; i < 4; i++) {
        const int f4 = t + i * 256;
        const int row = f4 >> 5, c4 = (f4 & 31) * 4;
        kreg[i] = __ldcs((const float4*)&ck[ckb + (size_t)(sbase + row) * KVD + c4]);
    }

    float mloc = -1e30f;

    for (int tile = 0; tile < SCHUNK / 32; tile++) {
        float* kb = kbuf + (tile & 1) * 4224;
#pragma unroll
        for (int i = 0; i < 4; i++) {
            const int f4 = t + i * 256;
            const int row = f4 >> 5, c4 = (f4 & 31) * 4;
            *(float4*)&kb[row * 132 + c4] = kreg[i];
        }
        __syncthreads();   // kb(tile) ready; part(tile-1) writes complete

        if (tile + 1 < SCHUNK / 32) {
#pragma unroll
            for (int i = 0; i < 4; i++) {
                const int f4 = t + i * 256;
                const int row = f4 >> 5, c4 = (f4 & 31) * 4;
                kreg[i] = __ldcs((const float4*)&ck[ckb + (size_t)(sbase + (tile + 1) * 32 + row) * KVD + c4]);
            }
        }

        if (tile >= 1 && t < 128) {
            const float* pp = part + ((tile - 1) & 1) * 1024;
            const int r = t >> 5;
            float val = 0.f;
#pragma unroll
            for (int d8 = 0; d8 < 8; d8++) val += pp[(d8 * 4 + r) * 32 + lane];
            const int sg = sbase + (tile - 1) * 32 + lane;
            if (sg == NEWPOS) val = -1e30f;
            sc[r * SCHUNK + (tile - 1) * 32 + lane] = val;
            mloc = fmaxf(mloc, val);
        }

        unsigned long long racc[4] = {0ull, 0ull, 0ull, 0ull};
#pragma unroll
        for (int c = 0; c < 4; c++) {
            ulonglong2 kk = *(const ulonglong2*)&kb[s_loc * 132 + base_d + c * 4];
#pragma unroll
            for (int r = 0; r < 4; r++) {
                ulonglong2 qq = *(const ulonglong2*)&qs[r * 128 + base_d + c * 4];
                racc[r] = f2fma(kk.x, qq.x, racc[r]);
                racc[r] = f2fma(kk.y, qq.y, racc[r]);
            }
        }
        float* pw = part + (tile & 1) * 1024;
#pragma unroll
        for (int r = 0; r < 4; r++) {
            float2 f = uf2(racc[r]);
            pw[(dg * 4 + r) * 32 + s_loc] = f.x + f.y;
        }
    }
    __syncthreads();

    if (t < 128) {
        const int lt = SCHUNK / 32 - 1;
        const float* pp = part + (lt & 1) * 1024;
        const int r = t >> 5;
        float val = 0.f;
#pragma unroll
        for (int d8 = 0; d8 < 8; d8++) val += pp[(d8 * 4 + r) * 32 + lane];
        const int sg = sbase + lt * 32 + lane;
        if (sg == NEWPOS) val = -1e30f;
        sc[r * SCHUNK + lt * 32 + lane] = val;
        mloc = fmaxf(mloc, val);
    }

    if (t < 128) {
#pragma unroll
        for (int off = 16; off; off >>= 1)
            mloc = fmaxf(mloc, __shfl_xor_sync(0xffffffffu, mloc, off));
        if (lane == 0) mf[t >> 5] = mloc;
    }
    __syncthreads();

    {
        const int r = t >> 6, s0 = t & 63;
        const float m = mf[r];
        float ls = 0.f;
#pragma unroll
        for (int j = 0; j < SCHUNK / 64; j++) {
            const int sl = s0 + j * 64;
            const float p = __expf(sc[r * SCHUNK + sl] - m);
            sc[r * SCHUNK + sl] = p;
            ls += p;
        }
#pragma unroll
        for (int off = 16; off; off >>= 1)
            ls += __shfl_xor_sync(0xffffffffu, ls, off);
        if (lane == 0) part[w] = ls;
    }
    __syncthreads();
    if (t < 4) {
        pm[bg * (NSPLIT * NREP) + split * NREP + t] = mf[t];
        pl[bg * (NSPLIT * NREP) + split * NREP + t] = part[2 * t] + part[2 * t + 1];
    }

    {
        const int dq = lane;
        const int sg8 = w;
        const size_t cvb = (size_t)(b * MAXSEQ) * KVD + g * HD + dq * 4;
        unsigned long long a[4][2];
#pragma unroll
        for (int r = 0; r < 4; r++) { a[r][0] = 0ull; a[r][1] = 0ull; }
        for (int i0 = 0; i0 < 32; i0 += 4) {
            float4 vf[4];
#pragma unroll
            for (int j = 0; j < 4; j++) {
                const int sl = sg8 * 32 + i0 + j;
                vf[j] = __ldcs((const float4*)&cv[cvb + (size_t)(sbase + sl) * KVD]);
            }
#pragma unroll
            for (int j = 0; j < 4; j++) {
                const int sl = sg8 * 32 + i0 + j;
                const unsigned long long vx = pack2(vf[j].x, vf[j].y);
                const unsigned long long vy = pack2(vf[j].z, vf[j].w);
#pragma unroll
                for (int r = 0; r < 4; r++) {
                    const unsigned long long pp = dupf(sc[r * SCHUNK + sl]);
                    a[r][0] = f2fma(pp, vx, a[r][0]);
                    a[r][1] = f2fma(pp, vy, a[r][1]);
                }
            }
        }
#pragma unroll
        for (int r = 0; r < 4; r++) {
            float2 f0 = uf2(a[r][0]), f1 = uf2(a[r][1]);
            float4 o4 = make_float4(f0.x, f0.y, f1.x, f1.y);
            *(float4*)&pvp[(sg8 * 4 + r) * 128 + dq * 4] = o4;
        }
    }
    __syncthreads();
#pragma unroll
    for (int i = 0; i < 2; i++) {
        const int idx = t + i * 256;
        const int r = idx >> 7, d = idx & 127;
        float v = 0.f;
#pragma unroll
        for (int sgp = 0; sgp < 8; sgp++) v += pvp[(sgp * 4 + r) * 128 + d];
        pacc[((bg * NSPLIT + split) * NREP + r) * HD + d] = v;
    }
}

// ------------------------------------------------------------------------------
// Combine partials + new token (s=4095). grid (256, 4), 128 threads.
// ------------------------------------------------------------------------------
__global__ __launch_bounds__(128)
void attn_combine(const float* __restrict__ q,
                  const float* __restrict__ kn,
                  const float* __restrict__ vn,
                  const float* __restrict__ pm,
                  const float* __restrict__ pl,
                  const float* __restrict__ pacc,
                  float* __restrict__ attn)
{
    const int bg = blockIdx.x;
    const int b = bg >> 3, g = bg & 7;
    const int rr = blockIdx.y;
    const int t = threadIdx.x, lane = t & 31;
    __shared__ float sn1;
    const float scale = 0.08838834764831845f;

    if (t < 32) {
        const float4 k4 = *(const float4*)&kn[(b * HKV + g) * HD + lane * 4];
        const float4 q4 = *(const float4*)&q[(b * HQ + g * NREP + rr) * HD + lane * 4];
        float ds = k4.x * q4.x + k4.y * q4.y + k4.z * q4.z + k4.w * q4.w;
#pragma unroll
        for (int off = 16; off; off >>= 1) ds += __shfl_xor_sync(0xffffffffu, ds, off);
        if (lane == 0) sn1 = ds * scale;
    }
    __syncthreads();

    const int d = t;
    const float vnew = vn[(b * HKV + g) * HD + d];

    float mi[NSPLIT];
    float M = sn1;
#pragma unroll
    for (int i = 0; i < NSPLIT; i++) {
        mi[i] = pm[bg * (NSPLIT * NREP) + i * NREP + rr];
        M = fmaxf(M, mi[i]);
    }
    const float en = __expf(sn1 - M);
    float L = en;
    float num = en * vnew;
#pragma unroll
    for (int i = 0; i < NSPLIT; i++) {
        const float e = __expf(mi[i] - M);
        L += pl[bg * (NSPLIT * NREP) + i * NREP + rr] * e;
        num += pacc[((bg * NSPLIT + i) * NREP + rr) * HD + d] * e;
    }
    attn[(b * HQ + g * NREP + rr) * HD + d] = num / L;
}

// ------------------------------------------------------------------------------
extern "C" void kernel_launch(void* const* d_in, const int* in_sizes, int n_in,
                              void* d_out, int out_size)
{
    const float* x  = (const float*)d_in[0];
    const float* ck = (const float*)d_in[1];
    const float* cv = (const float*)d_in[2];
    const float* wq = (const float*)d_in[3];
    const float* wk = (const float*)d_in[4];
    const float* wv = (const float*)d_in[5];
    const float* wo = (const float*)d_in[6];
    const float* fc = (const float*)d_in[7];
    const float* fs = (const float*)d_in[8];
    float* out = (float*)d_out;

    float *qkv, *qb, *kn, *vn, *pm, *pl, *pacc, *attn;
    cudaGetSymbolAddress((void**)&qkv,  g_qkv);
    cudaGetSymbolAddress((void**)&qb,   g_q);
    cudaGetSymbolAddress((void**)&kn,   g_kn);
    cudaGetSymbolAddress((void**)&vn,   g_vn);
    cudaGetSymbolAddress((void**)&pm,   g_pm);
    cudaGetSymbolAddress((void**)&pl,   g_pl);
    cudaGetSymbolAddress((void**)&pacc, g_pacc);
    cudaGetSymbolAddress((void**)&attn, g_attn);

    // 0) zero atomic accumulators (qkv sum + out)
    zero_bufs<<<640, 512>>>(qkv, out);
    // 1) fused QKV projection (scalar-FFMA, atomic k-split accumulate)
    gemm_s<<<dim3(QKV_OUTS / 256, KSPLIT), 256>>>(x, wq, wk, wv, DIM, KVD, qkv, QKV_OUTS);
    // 2) RoPE on summed qkv
    rope_reduce<<<384, 256>>>(qkv, fc, fs, qb, kn, vn);
    // 3) split attention over cached tokens (pos 4095 masked)
    attn_split<<<dim3(NB * HKV, NSPLIT), 256>>>(qb, ck, cv, pm, pl, pacc);
    // 4) combine + new token
    attn_combine<<<dim3(NB * HKV, NREP), 128>>>(qb, kn, vn, pm, pl, pacc, attn);
    // 5) output projection (scalar-FFMA, atomic accumulate directly into d_out)
    gemm_s<<<dim3(DIM / 256, KSPLIT), 256>>>(attn, wo, wo, wo, DIM, 0, out, DIM);
}

// round 15
// speedup vs baseline: 1.0622x; 1.0622x over previous
#include <cuda_runtime.h>
#include <cuda_bf16.h>
#include <math.h>

// Problem constants
#define NB     32      // batch
#define HQ     32
#define HKV    8
#define NREP   4
#define HD     128
#define DIM    4096    // HQ*HD
#define KVD    1024    // HKV*HD
#define MAXSEQ 4096
#define NEWPOS 4095

#define KSPLIT 16      // GEMM k-split
#define KB     256     // 4096 / KSPLIT
#define QKV_OUTS 6144  // 4096 + 1024 + 1024
#define NSPLIT 16      // attention seq splits
#define SCHUNK 256     // 4096 / 16

// ---------------- scratch (device globals; no allocations allowed) -------------
__device__ float g_qkvp[KSPLIT * NB * QKV_OUTS];   // qkv gemm partials (12.6MB)
__device__ float g_q   [NB * DIM];                  // rope'd q
__device__ float g_kn  [NB * KVD];                  // rope'd new k
__device__ float g_vn  [NB * KVD];                  // new v
__device__ float g_pm  [NB * HKV * NSPLIT * NREP];  // partial max
__device__ float g_pl  [NB * HKV * NSPLIT * NREP];  // partial sum
__device__ float g_pacc[NB * HKV * NSPLIT * NREP * HD]; // partial acc
__device__ float g_attn[NB * DIM];                  // attention output
__device__ float g_op  [KSPLIT * NB * DIM];         // wo gemm partials (8.4MB)

// ---------------- f32x2 helpers -------------------------------------------------
__device__ __forceinline__ unsigned long long f2fma(unsigned long long a,
                                                    unsigned long long b,
                                                    unsigned long long c) {
    unsigned long long d;
    asm("fma.rn.f32x2 %0, %1, %2, %3;" : "=l"(d) : "l"(a), "l"(b), "l"(c));
    return d;
}
__device__ __forceinline__ float2 uf2(unsigned long long u) {
    float2 f;
    asm("mov.b64 {%0, %1}, %2;" : "=f"(f.x), "=f"(f.y) : "l"(u));
    return f;
}
__device__ __forceinline__ unsigned long long dupf(float p) {
    unsigned long long u;
    asm("mov.b64 %0, {%1, %1};" : "=l"(u) : "f"(p));
    return u;
}
__device__ __forceinline__ unsigned long long pack2(float a, float b) {
    unsigned long long u;
    asm("mov.b64 %0, {%1, %2};" : "=l"(u) : "f"(a), "f"(b));
    return u;
}

// ------------------------------------------------------------------------------
// GEMM (f32x2 arm): QKV projection. 8 outs x 8 b per thread, pipelined LDG
// prefetch. grid (OUTS/256, KSPLIT), 128 threads. Single wave at KSPLIT=16.
// ------------------------------------------------------------------------------
__global__ __launch_bounds__(128)
void gemm_xwT(const float* __restrict__ x,
              const float* __restrict__ w0,
              const float* __restrict__ w1,
              const float* __restrict__ w2,
              int n0, int n1,
              float* __restrict__ yp, int OUTS)
{
    const int obase = blockIdx.x * 256;
    const float* wp;
    int orow;
    if (obase < n0)            { wp = w0; orow = obase; }
    else if (obase < n0 + n1)  { wp = w1; orow = obase - n0; }
    else                       { wp = w2; orow = obase - n0 - n1; }
    const int kb0 = blockIdx.y * KB;

    __shared__ __align__(16) float ws[16 * 264];   // [k][o:256 + pad]
    __shared__ __align__(16) float xs2[16 * 68];   // [k][b dup pairs]

    const int t    = threadIdx.x;
    const int lane = t & 31;
    const int w    = t >> 5;

    const int lxb = t >> 2;
    const int lxk = (t & 3) * 4;

    unsigned long long acc2[4][8];
#pragma unroll
    for (int p = 0; p < 4; p++)
#pragma unroll
        for (int i = 0; i < 8; i++) acc2[p][i] = 0ull;

    const int NT = KB / 16;

    float4 wv[8], xv;
#pragma unroll
    for (int h = 0; h < 2; h++)
#pragma unroll
        for (int q = 0; q < 4; q++)
            wv[h * 4 + q] = *(const float4*)&wp[(size_t)(orow + t + h * 128) * 4096 + kb0 + q * 4];
    xv = *(const float4*)&x[lxb * 4096 + kb0 + lxk];

    for (int kt = 0; kt < NT; kt++) {
        __syncthreads();
#pragma unroll
        for (int h = 0; h < 2; h++) {
            const int o = t + h * 128;
#pragma unroll
            for (int q = 0; q < 4; q++) {
                ws[(q * 4 + 0) * 264 + o] = wv[h * 4 + q].x;
                ws[(q * 4 + 1) * 264 + o] = wv[h * 4 + q].y;
                ws[(q * 4 + 2) * 264 + o] = wv[h * 4 + q].z;
                ws[(q * 4 + 3) * 264 + o] = wv[h * 4 + q].w;
            }
        }
        xs2[(lxk + 0) * 68 + lxb * 2] = xv.x; xs2[(lxk + 0) * 68 + lxb * 2 + 1] = xv.x;
        xs2[(lxk + 1) * 68 + lxb * 2] = xv.y; xs2[(lxk + 1) * 68 + lxb * 2 + 1] = xv.y;
        xs2[(lxk + 2) * 68 + lxb * 2] = xv.z; xs2[(lxk + 2) * 68 + lxb * 2 + 1] = xv.z;
        xs2[(lxk + 3) * 68 + lxb * 2] = xv.w; xs2[(lxk + 3) * 68 + lxb * 2 + 1] = xv.w;
        __syncthreads();

        if (kt + 1 < NT) {
            const int kbase = kb0 + (kt + 1) * 16;
#pragma unroll
            for (int h = 0; h < 2; h++)
#pragma unroll
                for (int q = 0; q < 4; q++)
                    wv[h * 4 + q] = *(const float4*)&wp[(size_t)(orow + t + h * 128) * 4096 + kbase + q * 4];
            xv = *(const float4*)&x[lxb * 4096 + kbase + lxk];
        }

#pragma unroll
        for (int kk = 0; kk < 16; kk++) {
            const ulonglong2 wA = *(const ulonglong2*)&ws[kk * 264 + lane * 4];
            const ulonglong2 wB = *(const ulonglong2*)&ws[kk * 264 + 128 + lane * 4];
#pragma unroll
            for (int i = 0; i < 8; i++) {
                const unsigned long long xp = *(const unsigned long long*)&xs2[kk * 68 + (w * 8 + i) * 2];
                acc2[0][i] = f2fma(wA.x, xp, acc2[0][i]);
                acc2[1][i] = f2fma(wA.y, xp, acc2[1][i]);
                acc2[2][i] = f2fma(wB.x, xp, acc2[2][i]);
                acc2[3][i] = f2fma(wB.y, xp, acc2[3][i]);
            }
        }
    }

#pragma unroll
    for (int p = 0; p < 4; p++) {
        const int o = obase + ((p < 2) ? 0 : 128) + lane * 4 + (p & 1) * 2;
#pragma unroll
        for (int i = 0; i < 8; i++) {
            const int b = w * 8 + i;
            float2 f = uf2(acc2[p][i]);
            *(float2*)&yp[(size_t)(blockIdx.y * NB + b) * OUTS + o] = f;
        }
    }
}

// ------------------------------------------------------------------------------
// GEMM (scalar-FFMA arm): wo projection. grid (DIM/256, KSPLIT), 256 threads.
// 4 o x 8 b thread tile, double-buffered smem. Single wave at KSPLIT=16.
// ------------------------------------------------------------------------------
__global__ __launch_bounds__(256)
void gemm_xwT_s(const float* __restrict__ x,
                const float* __restrict__ w0,
                float* __restrict__ yp)
{
    const int obase = blockIdx.x * 256;
    const int kb0 = blockIdx.y * KB;

    __shared__ __align__(16) float ws[2 * 16 * 264];  // [buf][k][o]
    __shared__ __align__(16) float xs[2 * 16 * 36];   // [buf][k][b]

    const int t    = threadIdx.x;
    const int lane = t & 31;
    const int w    = t >> 5;

    const int og = (w & 1) * 128 + lane * 4;   // 4 outs
    const int bq = (w >> 1) * 8;               // 8 batches

    const int lxb = t >> 2;          // x load: batch (t<128)
    const int lxk = (t & 3) * 4;     // x load: k offset

    float acc[4][8];
#pragma unroll
    for (int j = 0; j < 4; j++)
#pragma unroll
        for (int i = 0; i < 8; i++) acc[j][i] = 0.f;

    const int NT = KB / 16;

    float4 wv[4], xv;
#pragma unroll
    for (int q = 0; q < 4; q++)
        wv[q] = *(const float4*)&w0[(size_t)(obase + t) * 4096 + kb0 + q * 4];
    if (t < 128) xv = *(const float4*)&x[lxb * 4096 + kb0 + lxk];

    for (int kt = 0; kt < NT; kt++) {
        float* wsb = ws + (kt & 1) * (16 * 264);
        float* xsb = xs + (kt & 1) * (16 * 36);

#pragma unroll
        for (int q = 0; q < 4; q++) {
            wsb[(q * 4 + 0) * 264 + t] = wv[q].x;
            wsb[(q * 4 + 1) * 264 + t] = wv[q].y;
            wsb[(q * 4 + 2) * 264 + t] = wv[q].z;
            wsb[(q * 4 + 3) * 264 + t] = wv[q].w;
        }
        if (t < 128) {
            xsb[(lxk + 0) * 36 + lxb] = xv.x;
            xsb[(lxk + 1) * 36 + lxb] = xv.y;
            xsb[(lxk + 2) * 36 + lxb] = xv.z;
            xsb[(lxk + 3) * 36 + lxb] = xv.w;
        }
        __syncthreads();

        if (kt + 1 < NT) {
            const int kbase = kb0 + (kt + 1) * 16;
#pragma unroll
            for (int q = 0; q < 4; q++)
                wv[q] = *(const float4*)&w0[(size_t)(obase + t) * 4096 + kbase + q * 4];
            if (t < 128) xv = *(const float4*)&x[lxb * 4096 + kbase + lxk];
        }

#pragma unroll
        for (int kk = 0; kk < 16; kk++) {
            const float4 w4 = *(const float4*)&wsb[kk * 264 + og];
            const float4 xA = *(const float4*)&xsb[kk * 36 + bq];
            const float4 xB = *(const float4*)&xsb[kk * 36 + bq + 4];
            acc[0][0] += w4.x * xA.x; acc[0][1] += w4.x * xA.y;
            acc[0][2] += w4.x * xA.z; acc[0][3] += w4.x * xA.w;
            acc[0][4] += w4.x * xB.x; acc[0][5] += w4.x * xB.y;
            acc[0][6] += w4.x * xB.z; acc[0][7] += w4.x * xB.w;
            acc[1][0] += w4.y * xA.x; acc[1][1] += w4.y * xA.y;
            acc[1][2] += w4.y * xA.z; acc[1][3] += w4.y * xA.w;
            acc[1][4] += w4.y * xB.x; acc[1][5] += w4.y * xB.y;
            acc[1][6] += w4.y * xB.z; acc[1][7] += w4.y * xB.w;
            acc[2][0] += w4.z * xA.x; acc[2][1] += w4.z * xA.y;
            acc[2][2] += w4.z * xA.z; acc[2][3] += w4.z * xA.w;
            acc[2][4] += w4.z * xB.x; acc[2][5] += w4.z * xB.y;
            acc[2][6] += w4.z * xB.z; acc[2][7] += w4.z * xB.w;
            acc[3][0] += w4.w * xA.x; acc[3][1] += w4.w * xA.y;
            acc[3][2] += w4.w * xA.z; acc[3][3] += w4.w * xA.w;
            acc[3][4] += w4.w * xB.x; acc[3][5] += w4.w * xB.y;
            acc[3][6] += w4.w * xB.z; acc[3][7] += w4.w * xB.w;
        }
        __syncthreads();
    }

#pragma unroll
    for (int i = 0; i < 8; i++) {
        const int b = bq + i;
        float4 o4 = make_float4(acc[0][i], acc[1][i], acc[2][i], acc[3][i]);
        *(float4*)&yp[(size_t)(blockIdx.y * NB + b) * DIM + obase + og] = o4;
    }
}

// ------------------------------------------------------------------------------
// RoPE + k-split reduce. grid 384 x 256.
// ------------------------------------------------------------------------------
__global__ void rope_reduce(const float* __restrict__ qkvp,
                            const float* __restrict__ fc,
                            const float* __restrict__ fs,
                            float* __restrict__ qout,
                            float* __restrict__ kout,
                            float* __restrict__ vout)
{
    const int idx = blockIdx.x * 256 + threadIdx.x;  // < 98304
    const int b  = idx / 3072;
    const int jp = idx % 3072;
    const int j0 = jp * 2;

    float v0 = 0.f, v1 = 0.f;
#pragma unroll
    for (int s = 0; s < KSPLIT; s++) {
        const float* p = qkvp + (size_t)(s * NB + b) * QKV_OUTS + j0;
        v0 += p[0];
        v1 += p[1];
    }
    if (j0 < DIM + KVD) {
        const int i = jp & 63;
        const float c = fc[i], s_ = fs[i];
        const float re = v0 * c - v1 * s_;
        const float im = v0 * s_ + v1 * c;
        v0 = re; v1 = im;
    }
    if (j0 < DIM) {
        qout[b * DIM + j0] = v0;
        qout[b * DIM + j0 + 1] = v1;
    } else if (j0 < DIM + KVD) {
        kout[b * KVD + (j0 - DIM)] = v0;
        kout[b * KVD + (j0 - DIM) + 1] = v1;
    } else {
        vout[b * KVD + (j0 - DIM - KVD)] = v0;
        vout[b * KVD + (j0 - DIM - KVD) + 1] = v1;
    }
}

// ------------------------------------------------------------------------------
// Flash-decode split attention (one barrier per tile, double-buffered part).
// grid (256, 16), 256 threads, __ldcs streaming. smem ~48KB (4 CTA/SM).
// ------------------------------------------------------------------------------
__global__ __launch_bounds__(256, 4)
void attn_split(const float* __restrict__ q,
                const float* __restrict__ ck,
                const float* __restrict__ cv,
                float* __restrict__ pm,
                float* __restrict__ pl,
                float* __restrict__ pacc)
{
    const int bg = blockIdx.x;
    const int b = bg >> 3, g = bg & 7;
    const int split = blockIdx.y;
    const int t = threadIdx.x;
    const int lane = t & 31, w = t >> 5;
    const int sbase = split * SCHUNK;

    __shared__ __align__(16) float sm[12036];
    float* qs   = sm;              // [4][128]             512
    float* kbuf = sm + 512;        // 2 x [32][132]        8448  (aliased by pvp)
    float* sc   = sm + 8960;       // [4][256]             1024
    float* part = sm + 9984;       // 2 x [8][4][32]       2048
    float* mf   = sm + 12032;      // [4]
    float* pvp  = kbuf;            // alias, [8][4][128] = 4096

    const float scale = 0.08838834764831845f;  // 1/sqrt(128)

    for (int i = t; i < 512; i += 256) {
        const int r = i >> 7, d = i & 127;
        qs[r * 128 + d] = q[(b * HQ + g * NREP + r) * HD + d] * scale;
    }

    const int s_loc = t & 31;
    const int dg = t >> 5;
    const int base_d = dg * 16;
    const size_t ckb = (size_t)(b * MAXSEQ) * KVD + g * HD;

    float4 kreg[4];
#pragma unroll
    for (int i = 0; i < 4; i++) {
        const int f4 = t + i * 256;
        const int row = f4 >> 5, c4 = (f4 & 31) * 4;
        kreg[i] = __ldcs((const float4*)&ck[ckb + (size_t)(sbase + row) * KVD + c4]);
    }

    float mloc = -1e30f;

    for (int tile = 0; tile < SCHUNK / 32; tile++) {
        float* kb = kbuf + (tile & 1) * 4224;
#pragma unroll
        for (int i = 0; i < 4; i++) {
            const int f4 = t + i * 256;
            const int row = f4 >> 5, c4 = (f4 & 31) * 4;
            *(float4*)&kb[row * 132 + c4] = kreg[i];
        }
        __syncthreads();   // kb(tile) ready; part(tile-1) writes complete

        if (tile + 1 < SCHUNK / 32) {
#pragma unroll
            for (int i = 0; i < 4; i++) {
                const int f4 = t + i * 256;
                const int row = f4 >> 5, c4 = (f4 & 31) * 4;
                kreg[i] = __ldcs((const float4*)&ck[ckb + (size_t)(sbase + (tile + 1) * 32 + row) * KVD + c4]);
            }
        }

        if (tile >= 1 && t < 128) {
            const float* pp = part + ((tile - 1) & 1) * 1024;
            const int r = t >> 5;
            float val = 0.f;
#pragma unroll
            for (int d8 = 0; d8 < 8; d8++) val += pp[(d8 * 4 + r) * 32 + lane];
            const int sg = sbase + (tile - 1) * 32 + lane;
            if (sg == NEWPOS) val = -1e30f;
            sc[r * SCHUNK + (tile - 1) * 32 + lane] = val;
            mloc = fmaxf(mloc, val);
        }

        unsigned long long racc[4] = {0ull, 0ull, 0ull, 0ull};
#pragma unroll
        for (int c = 0; c < 4; c++) {
            ulonglong2 kk = *(const ulonglong2*)&kb[s_loc * 132 + base_d + c * 4];
#pragma unroll
            for (int r = 0; r < 4; r++) {
                ulonglong2 qq = *(const ulonglong2*)&qs[r * 128 + base_d + c * 4];
                racc[r] = f2fma(kk.x, qq.x, racc[r]);
                racc[r] = f2fma(kk.y, qq.y, racc[r]);
            }
        }
        float* pw = part + (tile & 1) * 1024;
#pragma unroll
        for (int r = 0; r < 4; r++) {
            float2 f = uf2(racc[r]);
            pw[(dg * 4 + r) * 32 + s_loc] = f.x + f.y;
        }
    }
    __syncthreads();

    if (t < 128) {
        const int lt = SCHUNK / 32 - 1;
        const float* pp = part + (lt & 1) * 1024;
        const int r = t >> 5;
        float val = 0.f;
#pragma unroll
        for (int d8 = 0; d8 < 8; d8++) val += pp[(d8 * 4 + r) * 32 + lane];
        const int sg = sbase + lt * 32 + lane;
        if (sg == NEWPOS) val = -1e30f;
        sc[r * SCHUNK + lt * 32 + lane] = val;
        mloc = fmaxf(mloc, val);
    }

    if (t < 128) {
#pragma unroll
        for (int off = 16; off; off >>= 1)
            mloc = fmaxf(mloc, __shfl_xor_sync(0xffffffffu, mloc, off));
        if (lane == 0) mf[t >> 5] = mloc;
    }
    __syncthreads();

    {
        const int r = t >> 6, s0 = t & 63;
        const float m = mf[r];
        float ls = 0.f;
#pragma unroll
        for (int j = 0; j < SCHUNK / 64; j++) {
            const int sl = s0 + j * 64;
            const float p = __expf(sc[r * SCHUNK + sl] - m);
            sc[r * SCHUNK + sl] = p;
            ls += p;
        }
#pragma unroll
        for (int off = 16; off; off >>= 1)
            ls += __shfl_xor_sync(0xffffffffu, ls, off);
        if (lane == 0) part[w] = ls;
    }
    __syncthreads();
    if (t < 4) {
        pm[bg * (NSPLIT * NREP) + split * NREP + t] = mf[t];
        pl[bg * (NSPLIT * NREP) + split * NREP + t] = part[2 * t] + part[2 * t + 1];
    }

    {
        const int dq = lane;
        const int sg8 = w;
        const size_t cvb = (size_t)(b * MAXSEQ) * KVD + g * HD + dq * 4;
        unsigned long long a[4][2];
#pragma unroll
        for (int r = 0; r < 4; r++) { a[r][0] = 0ull; a[r][1] = 0ull; }
        for (int i0 = 0; i0 < 32; i0 += 4) {
            float4 vf[4];
#pragma unroll
            for (int j = 0; j < 4; j++) {
                const int sl = sg8 * 32 + i0 + j;
                vf[j] = __ldcs((const float4*)&cv[cvb + (size_t)(sbase + sl) * KVD]);
            }
#pragma unroll
            for (int j = 0; j < 4; j++) {
                const int sl = sg8 * 32 + i0 + j;
                const unsigned long long vx = pack2(vf[j].x, vf[j].y);
                const unsigned long long vy = pack2(vf[j].z, vf[j].w);
#pragma unroll
                for (int r = 0; r < 4; r++) {
                    const unsigned long long pp = dupf(sc[r * SCHUNK + sl]);
                    a[r][0] = f2fma(pp, vx, a[r][0]);
                    a[r][1] = f2fma(pp, vy, a[r][1]);
                }
            }
        }
#pragma unroll
        for (int r = 0; r < 4; r++) {
            float2 f0 = uf2(a[r][0]), f1 = uf2(a[r][1]);
            float4 o4 = make_float4(f0.x, f0.y, f1.x, f1.y);
            *(float4*)&pvp[(sg8 * 4 + r) * 128 + dq * 4] = o4;
        }
    }
    __syncthreads();
#pragma unroll
    for (int i = 0; i < 2; i++) {
        const int idx = t + i * 256;
        const int r = idx >> 7, d = idx & 127;
        float v = 0.f;
#pragma unroll
        for (int sgp = 0; sgp < 8; sgp++) v += pvp[(sgp * 4 + r) * 128 + d];
        pacc[((bg * NSPLIT + split) * NREP + r) * HD + d] = v;
    }
}

// ------------------------------------------------------------------------------
// Combine partials + new token (s=4095). grid (256, 4), 128 threads.
// ------------------------------------------------------------------------------
__global__ __launch_bounds__(128)
void attn_combine(const float* __restrict__ q,
                  const float* __restrict__ kn,
                  const float* __restrict__ vn,
                  const float* __restrict__ pm,
                  const float* __restrict__ pl,
                  const float* __restrict__ pacc,
                  float* __restrict__ attn)
{
    const int bg = blockIdx.x;
    const int b = bg >> 3, g = bg & 7;
    const int rr = blockIdx.y;
    const int t = threadIdx.x, lane = t & 31;
    __shared__ float sn1;
    const float scale = 0.08838834764831845f;

    if (t < 32) {
        const float4 k4 = *(const float4*)&kn[(b * HKV + g) * HD + lane * 4];
        const float4 q4 = *(const float4*)&q[(b * HQ + g * NREP + rr) * HD + lane * 4];
        float ds = k4.x * q4.x + k4.y * q4.y + k4.z * q4.z + k4.w * q4.w;
#pragma unroll
        for (int off = 16; off; off >>= 1) ds += __shfl_xor_sync(0xffffffffu, ds, off);
        if (lane == 0) sn1 = ds * scale;
    }
    __syncthreads();

    const int d = t;
    const float vnew = vn[(b * HKV + g) * HD + d];

    float mi[NSPLIT];
    float M = sn1;
#pragma unroll
    for (int i = 0; i < NSPLIT; i++) {
        mi[i] = pm[bg * (NSPLIT * NREP) + i * NREP + rr];
        M = fmaxf(M, mi[i]);
    }
    const float en = __expf(sn1 - M);
    float L = en;
    float num = en * vnew;
#pragma unroll
    for (int i = 0; i < NSPLIT; i++) {
        const float e = __expf(mi[i] - M);
        L += pl[bg * (NSPLIT * NREP) + i * NREP + rr] * e;
        num += pacc[((bg * NSPLIT + i) * NREP + rr) * HD + d] * e;
    }
    attn[(b * HQ + g * NREP + rr) * HD + d] = num / L;
}

// ------------------------------------------------------------------------------
// Final k-split reduce of wo GEMM partials -> d_out.  grid 512 x 256.
// ------------------------------------------------------------------------------
__global__ void final_reduce(const float* __restrict__ op, float* __restrict__ out)
{
    const int idx = blockIdx.x * 256 + threadIdx.x;  // < 131072
    float v = 0.f;
#pragma unroll
    for (int s = 0; s < KSPLIT; s++) v += op[(size_t)s * NB * DIM + idx];
    out[idx] = v;
}

// ------------------------------------------------------------------------------
extern "C" void kernel_launch(void* const* d_in, const int* in_sizes, int n_in,
                              void* d_out, int out_size)
{
    const float* x  = (const float*)d_in[0];
    const float* ck = (const float*)d_in[1];
    const float* cv = (const float*)d_in[2];
    const float* wq = (const float*)d_in[3];
    const float* wk = (const float*)d_in[4];
    const float* wv = (const float*)d_in[5];
    const float* wo = (const float*)d_in[6];
    const float* fc = (const float*)d_in[7];
    const float* fs = (const float*)d_in[8];
    float* out = (float*)d_out;

    float *qkvp, *qb, *kn, *vn, *pm, *pl, *pacc, *attn, *op;
    cudaGetSymbolAddress((void**)&qkvp, g_qkvp);
    cudaGetSymbolAddress((void**)&qb,   g_q);
    cudaGetSymbolAddress((void**)&kn,   g_kn);
    cudaGetSymbolAddress((void**)&vn,   g_vn);
    cudaGetSymbolAddress((void**)&pm,   g_pm);
    cudaGetSymbolAddress((void**)&pl,   g_pl);
    cudaGetSymbolAddress((void**)&pacc, g_pacc);
    cudaGetSymbolAddress((void**)&attn, g_attn);
    cudaGetSymbolAddress((void**)&op,   g_op);

    // 1) fused QKV projection (f32x2 arm, KSPLIT=16 single wave)
    gemm_xwT<<<dim3(QKV_OUTS / 256, KSPLIT), 128>>>(x, wq, wk, wv, DIM, KVD, qkvp, QKV_OUTS);
    // 2) reduce partials + RoPE
    rope_reduce<<<384, 256>>>(qkvp, fc, fs, qb, kn, vn);
    // 3) split attention over cached tokens (pos 4095 masked)
    attn_split<<<dim3(NB * HKV, NSPLIT), 256>>>(qb, ck, cv, pm, pl, pacc);
    // 4) combine + new token
    attn_combine<<<dim3(NB * HKV, NREP), 128>>>(qb, kn, vn, pm, pl, pacc, attn);
    // 5) output projection (scalar-FFMA arm, KSPLIT=16 single wave)
    gemm_xwT_s<<<dim3(DIM / 256, KSPLIT), 256>>>(attn, wo, op);
    // 6) reduce to d_out
    final_reduce<<<512, 256>>>(op, out);
}

// round 16
// speedup vs baseline: 1.0695x; 1.0069x over previous
#include <cuda_runtime.h>
#include <cuda_bf16.h>
#include <math.h>

// Problem constants
#define NB     32      // batch
#define HQ     32
#define HKV    8
#define NREP   4
#define HD     128
#define DIM    4096    // HQ*HD
#define KVD    1024    // HKV*HD
#define MAXSEQ 4096
#define NEWPOS 4095

#define KSPLIT 16      // GEMM k-split
#define KB     256     // 4096 / KSPLIT
#define QKV_OUTS 6144  // 4096 + 1024 + 1024
#define NSPLIT 16      // attention seq splits
#define SCHUNK 256     // 4096 / 16

// ---------------- scratch (device globals; no allocations allowed) -------------
__device__ float g_qkvp[KSPLIT * NB * QKV_OUTS];   // qkv gemm partials (12.6MB)
__device__ float g_q   [NB * DIM];                  // rope'd q
__device__ float g_kn  [NB * KVD];                  // rope'd new k
__device__ float g_vn  [NB * KVD];                  // new v
__device__ float g_pm  [NB * HKV * NSPLIT * NREP];  // partial max
__device__ float g_pl  [NB * HKV * NSPLIT * NREP];  // partial sum
__device__ float g_pacc[NB * HKV * NSPLIT * NREP * HD]; // partial acc
__device__ float g_attn[NB * DIM];                  // attention output
__device__ float g_op  [KSPLIT * NB * DIM];         // wo gemm partials (8.4MB)

// ---------------- f32x2 helpers -------------------------------------------------
__device__ __forceinline__ unsigned long long f2fma(unsigned long long a,
                                                    unsigned long long b,
                                                    unsigned long long c) {
    unsigned long long d;
    asm("fma.rn.f32x2 %0, %1, %2, %3;" : "=l"(d) : "l"(a), "l"(b), "l"(c));
    return d;
}
__device__ __forceinline__ float2 uf2(unsigned long long u) {
    float2 f;
    asm("mov.b64 {%0, %1}, %2;" : "=f"(f.x), "=f"(f.y) : "l"(u));
    return f;
}
__device__ __forceinline__ unsigned long long dupf(float p) {
    unsigned long long u;
    asm("mov.b64 %0, {%1, %1};" : "=l"(u) : "f"(p));
    return u;
}
__device__ __forceinline__ unsigned long long pack2(float a, float b) {
    unsigned long long u;
    asm("mov.b64 %0, {%1, %2};" : "=l"(u) : "f"(a), "f"(b));
    return u;
}

// ------------------------------------------------------------------------------
// GEMM (f32x2 arm): QKV projection. 8 outs x 8 b per thread, pipelined LDG
// prefetch. grid (OUTS/256, KSPLIT), 128 threads. Single wave at KSPLIT=16.
// ------------------------------------------------------------------------------
__global__ __launch_bounds__(128)
void gemm_xwT(const float* __restrict__ x,
              const float* __restrict__ w0,
              const float* __restrict__ w1,
              const float* __restrict__ w2,
              int n0, int n1,
              float* __restrict__ yp, int OUTS)
{
    const int obase = blockIdx.x * 256;
    const float* wp;
    int orow;
    if (obase < n0)            { wp = w0; orow = obase; }
    else if (obase < n0 + n1)  { wp = w1; orow = obase - n0; }
    else                       { wp = w2; orow = obase - n0 - n1; }
    const int kb0 = blockIdx.y * KB;

    __shared__ __align__(16) float ws[16 * 264];   // [k][o:256 + pad]
    __shared__ __align__(16) float xs2[16 * 68];   // [k][b dup pairs]

    const int t    = threadIdx.x;
    const int lane = t & 31;
    const int w    = t >> 5;

    const int lxb = t >> 2;
    const int lxk = (t & 3) * 4;

    unsigned long long acc2[4][8];
#pragma unroll
    for (int p = 0; p < 4; p++)
#pragma unroll
        for (int i = 0; i < 8; i++) acc2[p][i] = 0ull;

    const int NT = KB / 16;

    float4 wv[8], xv;
#pragma unroll
    for (int h = 0; h < 2; h++)
#pragma unroll
        for (int q = 0; q < 4; q++)
            wv[h * 4 + q] = *(const float4*)&wp[(size_t)(orow + t + h * 128) * 4096 + kb0 + q * 4];
    xv = *(const float4*)&x[lxb * 4096 + kb0 + lxk];

    for (int kt = 0; kt < NT; kt++) {
        __syncthreads();
#pragma unroll
        for (int h = 0; h < 2; h++) {
            const int o = t + h * 128;
#pragma unroll
            for (int q = 0; q < 4; q++) {
                ws[(q * 4 + 0) * 264 + o] = wv[h * 4 + q].x;
                ws[(q * 4 + 1) * 264 + o] = wv[h * 4 + q].y;
                ws[(q * 4 + 2) * 264 + o] = wv[h * 4 + q].z;
                ws[(q * 4 + 3) * 264 + o] = wv[h * 4 + q].w;
            }
        }
        xs2[(lxk + 0) * 68 + lxb * 2] = xv.x; xs2[(lxk + 0) * 68 + lxb * 2 + 1] = xv.x;
        xs2[(lxk + 1) * 68 + lxb * 2] = xv.y; xs2[(lxk + 1) * 68 + lxb * 2 + 1] = xv.y;
        xs2[(lxk + 2) * 68 + lxb * 2] = xv.z; xs2[(lxk + 2) * 68 + lxb * 2 + 1] = xv.z;
        xs2[(lxk + 3) * 68 + lxb * 2] = xv.w; xs2[(lxk + 3) * 68 + lxb * 2 + 1] = xv.w;
        __syncthreads();

        if (kt + 1 < NT) {
            const int kbase = kb0 + (kt + 1) * 16;
#pragma unroll
            for (int h = 0; h < 2; h++)
#pragma unroll
                for (int q = 0; q < 4; q++)
                    wv[h * 4 + q] = *(const float4*)&wp[(size_t)(orow + t + h * 128) * 4096 + kbase + q * 4];
            xv = *(const float4*)&x[lxb * 4096 + kbase + lxk];
        }

#pragma unroll
        for (int kk = 0; kk < 16; kk++) {
            const ulonglong2 wA = *(const ulonglong2*)&ws[kk * 264 + lane * 4];
            const ulonglong2 wB = *(const ulonglong2*)&ws[kk * 264 + 128 + lane * 4];
#pragma unroll
            for (int i = 0; i < 8; i++) {
                const unsigned long long xp = *(const unsigned long long*)&xs2[kk * 68 + (w * 8 + i) * 2];
                acc2[0][i] = f2fma(wA.x, xp, acc2[0][i]);
                acc2[1][i] = f2fma(wA.y, xp, acc2[1][i]);
                acc2[2][i] = f2fma(wB.x, xp, acc2[2][i]);
                acc2[3][i] = f2fma(wB.y, xp, acc2[3][i]);
            }
        }
    }

#pragma unroll
    for (int p = 0; p < 4; p++) {
        const int o = obase + ((p < 2) ? 0 : 128) + lane * 4 + (p & 1) * 2;
#pragma unroll
        for (int i = 0; i < 8; i++) {
            const int b = w * 8 + i;
            float2 f = uf2(acc2[p][i]);
            *(float2*)&yp[(size_t)(blockIdx.y * NB + b) * OUTS + o] = f;
        }
    }
}

// ------------------------------------------------------------------------------
// GEMM (scalar-FFMA arm): wo projection. grid (DIM/256, KSPLIT), 256 threads.
// 4 o x 8 b thread tile, double-buffered smem. Single wave at KSPLIT=16.
// ------------------------------------------------------------------------------
__global__ __launch_bounds__(256)
void gemm_xwT_s(const float* __restrict__ x,
                const float* __restrict__ w0,
                float* __restrict__ yp)
{
    const int obase = blockIdx.x * 256;
    const int kb0 = blockIdx.y * KB;

    __shared__ __align__(16) float ws[2 * 16 * 264];  // [buf][k][o]
    __shared__ __align__(16) float xs[2 * 16 * 36];   // [buf][k][b]

    const int t    = threadIdx.x;
    const int lane = t & 31;
    const int w    = t >> 5;

    const int og = (w & 1) * 128 + lane * 4;   // 4 outs
    const int bq = (w >> 1) * 8;               // 8 batches

    const int lxb = t >> 2;          // x load: batch (t<128)
    const int lxk = (t & 3) * 4;     // x load: k offset

    float acc[4][8];
#pragma unroll
    for (int j = 0; j < 4; j++)
#pragma unroll
        for (int i = 0; i < 8; i++) acc[j][i] = 0.f;

    const int NT = KB / 16;

    float4 wv[4], xv;
#pragma unroll
    for (int q = 0; q < 4; q++)
        wv[q] = *(const float4*)&w0[(size_t)(obase + t) * 4096 + kb0 + q * 4];
    if (t < 128) xv = *(const float4*)&x[lxb * 4096 + kb0 + lxk];

    for (int kt = 0; kt < NT; kt++) {
        float* wsb = ws + (kt & 1) * (16 * 264);
        float* xsb = xs + (kt & 1) * (16 * 36);

#pragma unroll
        for (int q = 0; q < 4; q++) {
            wsb[(q * 4 + 0) * 264 + t] = wv[q].x;
            wsb[(q * 4 + 1) * 264 + t] = wv[q].y;
            wsb[(q * 4 + 2) * 264 + t] = wv[q].z;
            wsb[(q * 4 + 3) * 264 + t] = wv[q].w;
        }
        if (t < 128) {
            xsb[(lxk + 0) * 36 + lxb] = xv.x;
            xsb[(lxk + 1) * 36 + lxb] = xv.y;
            xsb[(lxk + 2) * 36 + lxb] = xv.z;
            xsb[(lxk + 3) * 36 + lxb] = xv.w;
        }
        __syncthreads();

        if (kt + 1 < NT) {
            const int kbase = kb0 + (kt + 1) * 16;
#pragma unroll
            for (int q = 0; q < 4; q++)
                wv[q] = *(const float4*)&w0[(size_t)(obase + t) * 4096 + kbase + q * 4];
            if (t < 128) xv = *(const float4*)&x[lxb * 4096 + kbase + lxk];
        }

#pragma unroll
        for (int kk = 0; kk < 16; kk++) {
            const float4 w4 = *(const float4*)&wsb[kk * 264 + og];
            const float4 xA = *(const float4*)&xsb[kk * 36 + bq];
            const float4 xB = *(const float4*)&xsb[kk * 36 + bq + 4];
            acc[0][0] += w4.x * xA.x; acc[0][1] += w4.x * xA.y;
            acc[0][2] += w4.x * xA.z; acc[0][3] += w4.x * xA.w;
            acc[0][4] += w4.x * xB.x; acc[0][5] += w4.x * xB.y;
            acc[0][6] += w4.x * xB.z; acc[0][7] += w4.x * xB.w;
            acc[1][0] += w4.y * xA.x; acc[1][1] += w4.y * xA.y;
            acc[1][2] += w4.y * xA.z; acc[1][3] += w4.y * xA.w;
            acc[1][4] += w4.y * xB.x; acc[1][5] += w4.y * xB.y;
            acc[1][6] += w4.y * xB.z; acc[1][7] += w4.y * xB.w;
            acc[2][0] += w4.z * xA.x; acc[2][1] += w4.z * xA.y;
            acc[2][2] += w4.z * xA.z; acc[2][3] += w4.z * xA.w;
            acc[2][4] += w4.z * xB.x; acc[2][5] += w4.z * xB.y;
            acc[2][6] += w4.z * xB.z; acc[2][7] += w4.z * xB.w;
            acc[3][0] += w4.w * xA.x; acc[3][1] += w4.w * xA.y;
            acc[3][2] += w4.w * xA.z; acc[3][3] += w4.w * xA.w;
            acc[3][4] += w4.w * xB.x; acc[3][5] += w4.w * xB.y;
            acc[3][6] += w4.w * xB.z; acc[3][7] += w4.w * xB.w;
        }
        __syncthreads();
    }

#pragma unroll
    for (int i = 0; i < 8; i++) {
        const int b = bq + i;
        float4 o4 = make_float4(acc[0][i], acc[1][i], acc[2][i], acc[3][i]);
        *(float4*)&yp[(size_t)(blockIdx.y * NB + b) * DIM + obase + og] = o4;
    }
}

// ------------------------------------------------------------------------------
// RoPE + k-split reduce (float2 partial loads). grid 384 x 256.
// ------------------------------------------------------------------------------
__global__ void rope_reduce(const float* __restrict__ qkvp,
                            const float* __restrict__ fc,
                            const float* __restrict__ fs,
                            float* __restrict__ qout,
                            float* __restrict__ kout,
                            float* __restrict__ vout)
{
    const int idx = blockIdx.x * 256 + threadIdx.x;  // < 98304
    const int b  = idx / 3072;
    const int jp = idx % 3072;
    const int j0 = jp * 2;

    float v0 = 0.f, v1 = 0.f;
#pragma unroll
    for (int s = 0; s < KSPLIT; s++) {
        const float2 p = *(const float2*)&qkvp[(size_t)(s * NB + b) * QKV_OUTS + j0];
        v0 += p.x;
        v1 += p.y;
    }
    if (j0 < DIM + KVD) {
        const int i = jp & 63;
        const float c = fc[i], s_ = fs[i];
        const float re = v0 * c - v1 * s_;
        const float im = v0 * s_ + v1 * c;
        v0 = re; v1 = im;
    }
    if (j0 < DIM) {
        *(float2*)&qout[b * DIM + j0] = make_float2(v0, v1);
    } else if (j0 < DIM + KVD) {
        *(float2*)&kout[b * KVD + (j0 - DIM)] = make_float2(v0, v1);
    } else {
        *(float2*)&vout[b * KVD + (j0 - DIM - KVD)] = make_float2(v0, v1);
    }
}

// ------------------------------------------------------------------------------
// Flash-decode split attention (one barrier per tile, double-buffered part).
// grid (256, 16), 256 threads, __ldcs streaming. smem ~48KB (4 CTA/SM).
// ------------------------------------------------------------------------------
__global__ __launch_bounds__(256, 4)
void attn_split(const float* __restrict__ q,
                const float* __restrict__ ck,
                const float* __restrict__ cv,
                float* __restrict__ pm,
                float* __restrict__ pl,
                float* __restrict__ pacc)
{
    const int bg = blockIdx.x;
    const int b = bg >> 3, g = bg & 7;
    const int split = blockIdx.y;
    const int t = threadIdx.x;
    const int lane = t & 31, w = t >> 5;
    const int sbase = split * SCHUNK;

    __shared__ __align__(16) float sm[12036];
    float* qs   = sm;              // [4][128]             512
    float* kbuf = sm + 512;        // 2 x [32][132]        8448  (aliased by pvp)
    float* sc   = sm + 8960;       // [4][256]             1024
    float* part = sm + 9984;       // 2 x [8][4][32]       2048
    float* mf   = sm + 12032;      // [4]
    float* pvp  = kbuf;            // alias, [8][4][128] = 4096

    const float scale = 0.08838834764831845f;  // 1/sqrt(128)

    for (int i = t; i < 512; i += 256) {
        const int r = i >> 7, d = i & 127;
        qs[r * 128 + d] = q[(b * HQ + g * NREP + r) * HD + d] * scale;
    }

    const int s_loc = t & 31;
    const int dg = t >> 5;
    const int base_d = dg * 16;
    const size_t ckb = (size_t)(b * MAXSEQ) * KVD + g * HD;

    float4 kreg[4];
#pragma unroll
    for (int i = 0; i < 4; i++) {
        const int f4 = t + i * 256;
        const int row = f4 >> 5, c4 = (f4 & 31) * 4;
        kreg[i] = __ldcs((const float4*)&ck[ckb + (size_t)(sbase + row) * KVD + c4]);
    }

    float mloc = -1e30f;

    for (int tile = 0; tile < SCHUNK / 32; tile++) {
        float* kb = kbuf + (tile & 1) * 4224;
#pragma unroll
        for (int i = 0; i < 4; i++) {
            const int f4 = t + i * 256;
            const int row = f4 >> 5, c4 = (f4 & 31) * 4;
            *(float4*)&kb[row * 132 + c4] = kreg[i];
        }
        __syncthreads();   // kb(tile) ready; part(tile-1) writes complete

        if (tile + 1 < SCHUNK / 32) {
#pragma unroll
            for (int i = 0; i < 4; i++) {
                const int f4 = t + i * 256;
                const int row = f4 >> 5, c4 = (f4 & 31) * 4;
                kreg[i] = __ldcs((const float4*)&ck[ckb + (size_t)(sbase + (tile + 1) * 32 + row) * KVD + c4]);
            }
        }

        if (tile >= 1 && t < 128) {
            const float* pp = part + ((tile - 1) & 1) * 1024;
            const int r = t >> 5;
            float val = 0.f;
#pragma unroll
            for (int d8 = 0; d8 < 8; d8++) val += pp[(d8 * 4 + r) * 32 + lane];
            const int sg = sbase + (tile - 1) * 32 + lane;
            if (sg == NEWPOS) val = -1e30f;
            sc[r * SCHUNK + (tile - 1) * 32 + lane] = val;
            mloc = fmaxf(mloc, val);
        }

        unsigned long long racc[4] = {0ull, 0ull, 0ull, 0ull};
#pragma unroll
        for (int c = 0; c < 4; c++) {
            ulonglong2 kk = *(const ulonglong2*)&kb[s_loc * 132 + base_d + c * 4];
#pragma unroll
            for (int r = 0; r < 4; r++) {
                ulonglong2 qq = *(const ulonglong2*)&qs[r * 128 + base_d + c * 4];
                racc[r] = f2fma(kk.x, qq.x, racc[r]);
                racc[r] = f2fma(kk.y, qq.y, racc[r]);
            }
        }
        float* pw = part + (tile & 1) * 1024;
#pragma unroll
        for (int r = 0; r < 4; r++) {
            float2 f = uf2(racc[r]);
            pw[(dg * 4 + r) * 32 + s_loc] = f.x + f.y;
        }
    }
    __syncthreads();

    if (t < 128) {
        const int lt = SCHUNK / 32 - 1;
        const float* pp = part + (lt & 1) * 1024;
        const int r = t >> 5;
        float val = 0.f;
#pragma unroll
        for (int d8 = 0; d8 < 8; d8++) val += pp[(d8 * 4 + r) * 32 + lane];
        const int sg = sbase + lt * 32 + lane;
        if (sg == NEWPOS) val = -1e30f;
        sc[r * SCHUNK + lt * 32 + lane] = val;
        mloc = fmaxf(mloc, val);
    }

    if (t < 128) {
#pragma unroll
        for (int off = 16; off; off >>= 1)
            mloc = fmaxf(mloc, __shfl_xor_sync(0xffffffffu, mloc, off));
        if (lane == 0) mf[t >> 5] = mloc;
    }
    __syncthreads();

    {
        const int r = t >> 6, s0 = t & 63;
        const float m = mf[r];
        float ls = 0.f;
#pragma unroll
        for (int j = 0; j < SCHUNK / 64; j++) {
            const int sl = s0 + j * 64;
            const float p = __expf(sc[r * SCHUNK + sl] - m);
            sc[r * SCHUNK + sl] = p;
            ls += p;
        }
#pragma unroll
        for (int off = 16; off; off >>= 1)
            ls += __shfl_xor_sync(0xffffffffu, ls, off);
        if (lane == 0) part[w] = ls;
    }
    __syncthreads();
    if (t < 4) {
        pm[bg * (NSPLIT * NREP) + split * NREP + t] = mf[t];
        pl[bg * (NSPLIT * NREP) + split * NREP + t] = part[2 * t] + part[2 * t + 1];
    }

    {
        const int dq = lane;
        const int sg8 = w;
        const size_t cvb = (size_t)(b * MAXSEQ) * KVD + g * HD + dq * 4;
        unsigned long long a[4][2];
#pragma unroll
        for (int r = 0; r < 4; r++) { a[r][0] = 0ull; a[r][1] = 0ull; }
        for (int i0 = 0; i0 < 32; i0 += 4) {
            float4 vf[4];
#pragma unroll
            for (int j = 0; j < 4; j++) {
                const int sl = sg8 * 32 + i0 + j;
                vf[j] = __ldcs((const float4*)&cv[cvb + (size_t)(sbase + sl) * KVD]);
            }
#pragma unroll
            for (int j = 0; j < 4; j++) {
                const int sl = sg8 * 32 + i0 + j;
                const unsigned long long vx = pack2(vf[j].x, vf[j].y);
                const unsigned long long vy = pack2(vf[j].z, vf[j].w);
#pragma unroll
                for (int r = 0; r < 4; r++) {
                    const unsigned long long pp = dupf(sc[r * SCHUNK + sl]);
                    a[r][0] = f2fma(pp, vx, a[r][0]);
                    a[r][1] = f2fma(pp, vy, a[r][1]);
                }
            }
        }
#pragma unroll
        for (int r = 0; r < 4; r++) {
            float2 f0 = uf2(a[r][0]), f1 = uf2(a[r][1]);
            float4 o4 = make_float4(f0.x, f0.y, f1.x, f1.y);
            *(float4*)&pvp[(sg8 * 4 + r) * 128 + dq * 4] = o4;
        }
    }
    __syncthreads();
#pragma unroll
    for (int i = 0; i < 2; i++) {
        const int idx = t + i * 256;
        const int r = idx >> 7, d = idx & 127;
        float v = 0.f;
#pragma unroll
        for (int sgp = 0; sgp < 8; sgp++) v += pvp[(sgp * 4 + r) * 128 + d];
        pacc[((bg * NSPLIT + split) * NREP + r) * HD + d] = v;
    }
}

// ------------------------------------------------------------------------------
// Combine partials + new token (s=4095). grid 256, 512 threads: t -> (rep, d).
// ------------------------------------------------------------------------------
__global__ __launch_bounds__(512)
void attn_combine(const float* __restrict__ q,
                  const float* __restrict__ kn,
                  const float* __restrict__ vn,
                  const float* __restrict__ pm,
                  const float* __restrict__ pl,
                  const float* __restrict__ pacc,
                  float* __restrict__ attn)
{
    const int bg = blockIdx.x;
    const int b = bg >> 3, g = bg & 7;
    const int t = threadIdx.x, lane = t & 31;
    __shared__ float sn[4];
    const float scale = 0.08838834764831845f;

    if (t < 128) {
        const int r = t >> 5;
        const float4 k4 = *(const float4*)&kn[(b * HKV + g) * HD + lane * 4];
        const float4 q4 = *(const float4*)&q[(b * HQ + g * NREP + r) * HD + lane * 4];
        float ds = k4.x * q4.x + k4.y * q4.y + k4.z * q4.z + k4.w * q4.w;
#pragma unroll
        for (int off = 16; off; off >>= 1) ds += __shfl_xor_sync(0xffffffffu, ds, off);
        if (lane == 0) sn[r] = ds * scale;
    }
    __syncthreads();

    const int rr = t >> 7, d = t & 127;
    const float vnew = vn[(b * HKV + g) * HD + d];

    float mi[NSPLIT];
    float M = sn[rr];
#pragma unroll
    for (int i = 0; i < NSPLIT; i++) {
        mi[i] = pm[bg * (NSPLIT * NREP) + i * NREP + rr];
        M = fmaxf(M, mi[i]);
    }
    const float en = __expf(sn[rr] - M);
    float L = en;
    float num = en * vnew;
#pragma unroll
    for (int i = 0; i < NSPLIT; i++) {
        const float e = __expf(mi[i] - M);
        L += pl[bg * (NSPLIT * NREP) + i * NREP + rr] * e;
        num += pacc[((bg * NSPLIT + i) * NREP + rr) * HD + d] * e;
    }
    attn[(b * HQ + g * NREP + rr) * HD + d] = num / L;
}

// ------------------------------------------------------------------------------
// Final k-split reduce of wo GEMM partials -> d_out.  grid 512 x 256.
// ------------------------------------------------------------------------------
__global__ void final_reduce(const float* __restrict__ op, float* __restrict__ out)
{
    const int idx = blockIdx.x * 256 + threadIdx.x;  // < 131072
    float v = 0.f;
#pragma unroll
    for (int s = 0; s < KSPLIT; s++) v += op[(size_t)s * NB * DIM + idx];
    out[idx] = v;
}

// ------------------------------------------------------------------------------
extern "C" void kernel_launch(void* const* d_in, const int* in_sizes, int n_in,
                              void* d_out, int out_size)
{
    const float* x  = (const float*)d_in[0];
    const float* ck = (const float*)d_in[1];
    const float* cv = (const float*)d_in[2];
    const float* wq = (const float*)d_in[3];
    const float* wk = (const float*)d_in[4];
    const float* wv = (const float*)d_in[5];
    const float* wo = (const float*)d_in[6];
    const float* fc = (const float*)d_in[7];
    const float* fs = (const float*)d_in[8];
    float* out = (float*)d_out;

    float *qkvp, *qb, *kn, *vn, *pm, *pl, *pacc, *attn, *op;
    cudaGetSymbolAddress((void**)&qkvp, g_qkvp);
    cudaGetSymbolAddress((void**)&qb,   g_q);
    cudaGetSymbolAddress((void**)&kn,   g_kn);
    cudaGetSymbolAddress((void**)&vn,   g_vn);
    cudaGetSymbolAddress((void**)&pm,   g_pm);
    cudaGetSymbolAddress((void**)&pl,   g_pl);
    cudaGetSymbolAddress((void**)&pacc, g_pacc);
    cudaGetSymbolAddress((void**)&attn, g_attn);
    cudaGetSymbolAddress((void**)&op,   g_op);

    // 1) fused QKV projection (f32x2 arm, KSPLIT=16 single wave)
    gemm_xwT<<<dim3(QKV_OUTS / 256, KSPLIT), 128>>>(x, wq, wk, wv, DIM, KVD, qkvp, QKV_OUTS);
    // 2) reduce partials + RoPE
    rope_reduce<<<384, 256>>>(qkvp, fc, fs, qb, kn, vn);
    // 3) split attention over cached tokens (pos 4095 masked)
    attn_split<<<dim3(NB * HKV, NSPLIT), 256>>>(qb, ck, cv, pm, pl, pacc);
    // 4) combine + new token (512-thread blocks)
    attn_combine<<<NB * HKV, 512>>>(qb, kn, vn, pm, pl, pacc, attn);
    // 5) output projection (scalar-FFMA arm, KSPLIT=16 single wave)
    gemm_xwT_s<<<dim3(DIM / 256, KSPLIT), 256>>>(attn, wo, op);
    // 6) reduce to d_out
    final_reduce<<<512, 256>>>(op, out);
}